// round 4
// baseline (speedup 1.0000x reference)
#include <cuda_runtime.h>
#include <cuda_bf16.h>
#include <math.h>

// Problem constants (fixed by dataset): N=100000, E=1600000, dims 128->64->32
#define IN_F  128
#define HID_F 64
#define OUT_F 32
#define N_MAX 100000
#define E_MAX 1600000
#define NB_MAX 512         // ceil(N/256) = 391 < 512

// ---- device scratch (no cudaMalloc allowed) ----
__device__ int   g_deg    [N_MAX];       // 1 + in-degree
__device__ float g_dinv   [N_MAX];
__device__ int   g_rowstart[N_MAX];      // CSR offsets (in-degree only)
__device__ int   g_cursor [N_MAX];       // fill cursors
__device__ int   g_bsum   [NB_MAX];      // per-block indegree sums
__device__ int   g_bofs   [NB_MAX];      // exclusive scan of block sums
__device__ int   g_csr_src[E_MAX];
__device__ float g_csr_w  [E_MAX];
__device__ float g_H1  [(size_t)N_MAX * HID_F];   // x @ W1
__device__ float g_agg1[(size_t)N_MAX * HID_F];   // relu(aggregated layer-1)
__device__ float g_H2  [(size_t)N_MAX * OUT_F];   // relu_agg1 @ W2

// ---------------------------------------------------------------------------
// K0: deg init to 1 (self loop)
__global__ void k_deg_init(int N) {
    int n = blockIdx.x * blockDim.x + threadIdx.x;
    if (n < N) g_deg[n] = 1;
}

// K1: histogram in-degree. edge_index is INT32 (JAX default x64-disabled
// downgrades jnp.int64 -> int32; reading it as int64 packed two indices into
// one "index" -> wild atomic addresses -> CUDA 717 in rounds 1-3).
__global__ void k_edge_prep(const int* __restrict__ ei, int E) {
    int e = blockIdx.x * blockDim.x + threadIdx.x;
    if (e < E) {
        int d = ei[E + e];
        atomicAdd(&g_deg[d], 1);
    }
}

// K2: dinv = rsqrt(deg)
__global__ void k_dinv(int N) {
    int n = blockIdx.x * blockDim.x + threadIdx.x;
    if (n < N) g_dinv[n] = rsqrtf((float)g_deg[n]);
}

// ---------------------------------------------------------------------------
// Exclusive scan of in-degrees (deg-1) over N nodes, 256 nodes per block.
// SA: per-block sums
__global__ __launch_bounds__(256) void k_scan_a(int N) {
    __shared__ int sh[256];
    int t = threadIdx.x;
    int n = blockIdx.x * 256 + t;
    sh[t] = (n < N) ? (g_deg[n] - 1) : 0;
    __syncthreads();
    for (int off = 128; off > 0; off >>= 1) {
        if (t < off) sh[t] += sh[t + off];
        __syncthreads();
    }
    if (t == 0) g_bsum[blockIdx.x] = sh[0];
}

// SB: exclusive scan of block sums (single block; NB <= 512, trivial serial)
__global__ void k_scan_b(int NB) {
    if (threadIdx.x == 0) {
        int run = 0;
        for (int i = 0; i < NB; ++i) { g_bofs[i] = run; run += g_bsum[i]; }
    }
}

// SC: in-block exclusive scan + block offset -> row_start, cursor
__global__ __launch_bounds__(256) void k_scan_c(int N) {
    __shared__ int sh[256];
    int t = threadIdx.x;
    int n = blockIdx.x * 256 + t;
    int v = (n < N) ? (g_deg[n] - 1) : 0;
    sh[t] = v;
    __syncthreads();
    // Hillis-Steele inclusive scan
    for (int off = 1; off < 256; off <<= 1) {
        int add = (t >= off) ? sh[t - off] : 0;
        __syncthreads();
        sh[t] += add;
        __syncthreads();
    }
    if (n < N) {
        int excl = sh[t] - v + g_bofs[blockIdx.x];
        g_rowstart[n] = excl;
        g_cursor[n]   = excl;
    }
}

// Fill CSR: slot per edge via int atomic cursor; fold normalization coefficient
__global__ void k_fill(const int* __restrict__ ei, int E) {
    int e = blockIdx.x * blockDim.x + threadIdx.x;
    if (e < E) {
        int s = ei[e];
        int d = ei[E + e];
        int pos = atomicAdd(&g_cursor[d], 1);
        g_csr_src[pos] = s;
        g_csr_w[pos]   = g_dinv[s] * g_dinv[d];
    }
}

// ---------------------------------------------------------------------------
// GEMM1: H1[N,64] = x[N,128] @ W1[128,64]; 32-row tiles, W1 + x tile in SMEM
__global__ __launch_bounds__(256) void k_gemm1(const float* __restrict__ x,
                                               const float* __restrict__ W,
                                               int N) {
    __shared__ float Ws[IN_F * HID_F];   // 32 KB
    __shared__ float xs[32 * IN_F];      // 16 KB
    int t = threadIdx.x;
    for (int i = t; i < IN_F * HID_F; i += 256) Ws[i] = W[i];

    int row0 = blockIdx.x * 32;
    int rows = N - row0; if (rows > 32) rows = 32;

    const float4* xg  = (const float4*)(x + (size_t)row0 * IN_F);
    float4*       xs4 = (float4*)xs;
    const int NV = 32 * IN_F / 4;  // 1024
    for (int i = t; i < NV; i += 256) {
        int r = i / (IN_F / 4);
        xs4[i] = (r < rows) ? xg[i] : make_float4(0.f, 0.f, 0.f, 0.f);
    }
    __syncthreads();

    int r = t >> 3;            // 0..31
    int g = (t & 7) * 8;       // col group: 0,8,...,56
    if (r < rows) {
        float acc[8];
        #pragma unroll
        for (int i = 0; i < 8; ++i) acc[i] = 0.f;
        #pragma unroll 16
        for (int k = 0; k < IN_F; ++k) {
            float xv = xs[r * IN_F + k];
            float4 w0 = *(const float4*)&Ws[k * HID_F + g];
            float4 w1 = *(const float4*)&Ws[k * HID_F + g + 4];
            acc[0] = fmaf(xv, w0.x, acc[0]);
            acc[1] = fmaf(xv, w0.y, acc[1]);
            acc[2] = fmaf(xv, w0.z, acc[2]);
            acc[3] = fmaf(xv, w0.w, acc[3]);
            acc[4] = fmaf(xv, w1.x, acc[4]);
            acc[5] = fmaf(xv, w1.y, acc[5]);
            acc[6] = fmaf(xv, w1.z, acc[6]);
            acc[7] = fmaf(xv, w1.w, acc[7]);
        }
        float* out = g_H1 + (size_t)(row0 + r) * HID_F + g;
        *(float4*)(out)     = make_float4(acc[0], acc[1], acc[2], acc[3]);
        *(float4*)(out + 4) = make_float4(acc[4], acc[5], acc[6], acc[7]);
    }
}

// GEMM2: H2[N,32] = agg1[N,64] @ W2[64,32]  (agg1 already relu'd)
__global__ __launch_bounds__(256) void k_gemm2(const float* __restrict__ W, int N) {
    __shared__ float Ws[HID_F * OUT_F];  // 8 KB
    __shared__ float xs[32 * HID_F];     // 8 KB
    int t = threadIdx.x;
    for (int i = t; i < HID_F * OUT_F; i += 256) Ws[i] = W[i];

    int row0 = blockIdx.x * 32;
    int rows = N - row0; if (rows > 32) rows = 32;

    const float4* xg  = (const float4*)(g_agg1 + (size_t)row0 * HID_F);
    float4*       xs4 = (float4*)xs;
    const int NV = 32 * HID_F / 4;  // 512
    for (int i = t; i < NV; i += 256) {
        int r = i / (HID_F / 4);
        xs4[i] = (r < rows) ? xg[i] : make_float4(0.f, 0.f, 0.f, 0.f);
    }
    __syncthreads();

    int r = t >> 3;          // 0..31
    int g = (t & 7) * 4;     // col group: 0,4,...,28
    if (r < rows) {
        float acc[4] = {0.f, 0.f, 0.f, 0.f};
        #pragma unroll 16
        for (int k = 0; k < HID_F; ++k) {
            float xv = xs[r * HID_F + k];
            float4 w = *(const float4*)&Ws[k * OUT_F + g];
            acc[0] = fmaf(xv, w.x, acc[0]);
            acc[1] = fmaf(xv, w.y, acc[1]);
            acc[2] = fmaf(xv, w.z, acc[2]);
            acc[3] = fmaf(xv, w.w, acc[3]);
        }
        float* out = g_H2 + (size_t)(row0 + r) * OUT_F + g;
        *(float4*)out = make_float4(acc[0], acc[1], acc[2], acc[3]);
    }
}

// ---------------------------------------------------------------------------
// Gather1: one warp per node. acc = H1[n]*dinv^2 + b1 + sum_j w_j * H1[s_j].
// 2 features per lane (float2). ReLU fused into store.
__global__ __launch_bounds__(256) void k_gather1(const float* __restrict__ b1, int N) {
    int wid  = (blockIdx.x * blockDim.x + threadIdx.x) >> 5;
    int lane = threadIdx.x & 31;
    if (wid >= N) return;
    int n = wid;

    float dn = g_dinv[n];
    float c  = dn * dn;
    float2 h  = *(const float2*)&g_H1[(size_t)n * HID_F + lane * 2];
    float2 bb = *(const float2*)&b1[lane * 2];
    float2 acc;
    acc.x = fmaf(h.x, c, bb.x);
    acc.y = fmaf(h.y, c, bb.y);

    int start = g_rowstart[n];
    int end   = start + g_deg[n] - 1;
    for (int j = start; j < end; ++j) {
        int   s = g_csr_src[j];
        float w = g_csr_w[j];
        float2 v = *(const float2*)&g_H1[(size_t)s * HID_F + lane * 2];
        acc.x = fmaf(w, v.x, acc.x);
        acc.y = fmaf(w, v.y, acc.y);
    }
    float2 o;
    o.x = fmaxf(acc.x, 0.f);
    o.y = fmaxf(acc.y, 0.f);
    *(float2*)&g_agg1[(size_t)n * HID_F + lane * 2] = o;
}

// Gather2: one warp per node, 1 feature per lane, writes d_out.
__global__ __launch_bounds__(256) void k_gather2(const float* __restrict__ b2,
                                                 float* __restrict__ out, int N) {
    int wid  = (blockIdx.x * blockDim.x + threadIdx.x) >> 5;
    int lane = threadIdx.x & 31;
    if (wid >= N) return;
    int n = wid;

    float dn = g_dinv[n];
    float c  = dn * dn;
    float acc = fmaf(g_H2[(size_t)n * OUT_F + lane], c, b2[lane]);

    int start = g_rowstart[n];
    int end   = start + g_deg[n] - 1;
    for (int j = start; j < end; ++j) {
        int   s = g_csr_src[j];
        float w = g_csr_w[j];
        acc = fmaf(w, g_H2[(size_t)s * OUT_F + lane], acc);
    }
    out[(size_t)n * OUT_F + lane] = acc;
}

// ---------------------------------------------------------------------------
extern "C" void kernel_launch(void* const* d_in, const int* in_sizes, int n_in,
                              void* d_out, int out_size) {
    const float* x  = (const float*)d_in[0];
    const int*   ei = (const int*)d_in[1];      // int32! (JAX x64 disabled)
    const float* W1 = (const float*)d_in[2];
    const float* b1 = (const float*)d_in[3];
    const float* W2 = (const float*)d_in[4];
    const float* b2 = (const float*)d_in[5];
    float*       out = (float*)d_out;

    const int N = in_sizes[0] / IN_F;     // 100000
    const int E = in_sizes[1] / 2;        // 1600000
    const int NB = (N + 255) / 256;       // scan blocks

    const int T = 256;
    // degree + dinv
    k_deg_init <<<(N + T - 1) / T, T>>>(N);
    k_edge_prep<<<(E + T - 1) / T, T>>>(ei, E);
    k_dinv     <<<(N + T - 1) / T, T>>>(N);

    // CSR build (int atomics only)
    k_scan_a<<<NB, 256>>>(N);
    k_scan_b<<<1, 32>>>(NB);
    k_scan_c<<<NB, 256>>>(N);
    k_fill  <<<(E + T - 1) / T, T>>>(ei, E);

    // layer 1: GEMM -> gather (relu fused)
    k_gemm1  <<<(N + 31) / 32, 256>>>(x, W1, N);
    k_gather1<<<(N * 32 + T - 1) / T, T>>>(b1, N);

    // layer 2: GEMM -> gather (writes d_out)
    k_gemm2  <<<(N + 31) / 32, 256>>>(W2, N);
    k_gather2<<<(N * 32 + T - 1) / T, T>>>(b2, out, N);
}